// round 3
// baseline (speedup 1.0000x reference)
#include <cuda_runtime.h>
#include <math.h>

#define NN 16384
#define NE 262144
#define NF 128
#define ND 64
#define NC 40
#define RK 16

// ---------------- scratch (device globals; no allocation allowed) ----------
__device__ float g_xl  [NN * ND];   // x @ W1l   (gathered in layer 1)
__device__ float g_xr  [NN * ND];   // x @ W1r   (self part layer 1)
__device__ float g_h1  [NN * ND];
__device__ float g_h1l [NN * ND];   // h1 @ W2l  (gathered in layer 2)
__device__ float g_h1r [NN * ND];   // h1 @ W2r  (self part layer 2)
__device__ float g_h2  [NN * ND];
__device__ float g_phi [NN * RK];
__device__ float g_T   [RK * 65];
// CSR structures
__device__ int   g_cnti[NN];
__device__ int   g_off [NN + 1];
__device__ int   g_cur [NN];
__device__ int   g_nbr [NE];

// c_k = sqrt(2^k / k!)
__constant__ float c_coef[RK] = {
    1.0f,          1.41421356f,  1.41421356f,  1.15470054f,
    0.81649658f,   0.51639778f,  0.29814240f,  0.15936387f,
    0.07968194f,   0.03756241f,  0.01679842f,  0.00716286f,
    0.00292422f,   0.00114698f,  4.33517e-4f,  1.58298e-4f};

// ---------------- zero counters / T ------------------------------------------
__global__ void zero_kernel() {
    int idx = blockIdx.x * blockDim.x + threadIdx.x;
    if (idx < NN) g_cnti[idx] = 0;
    if (idx < RK * 65) g_T[idx] = 0.f;
}

// ---------------- CSR build: count, scan, fill -------------------------------
__global__ __launch_bounds__(256) void count_kernel(const int* __restrict__ ei) {
    int t = blockIdx.x * 256 + threadIdx.x;
    int dst = __ldg(ei + NE + t);
    atomicAdd(g_cnti + dst, 1);
}

__global__ __launch_bounds__(1024) void scan_kernel() {
    __shared__ int s[1024];
    int tid = threadIdx.x;
    int base = tid * 16;
    int v[16];
    int run = 0;
#pragma unroll
    for (int j = 0; j < 16; j++) { v[j] = run; run += g_cnti[base + j]; }
    s[tid] = run;
    __syncthreads();
    // inclusive scan over s (Hillis-Steele)
    for (int off = 1; off < 1024; off <<= 1) {
        int t = (tid >= off) ? s[tid - off] : 0;
        __syncthreads();
        s[tid] += t;
        __syncthreads();
    }
    int pre = (tid == 0) ? 0 : s[tid - 1];
#pragma unroll
    for (int j = 0; j < 16; j++) {
        int o = pre + v[j];
        g_off[base + j] = o;
        g_cur[base + j] = o;
    }
    if (tid == 1023) g_off[NN] = NE;
}

__global__ __launch_bounds__(256) void fill_kernel(const int* __restrict__ ei) {
    int t = blockIdx.x * 256 + threadIdx.x;
    int src = __ldg(ei + t);
    int dst = __ldg(ei + NE + t);
    int p = atomicAdd(g_cur + dst, 1);
    g_nbr[p] = src;
}

// ---- fused dual GEMM: outl = A @ Wl, outr = A @ Wr  (A:[NN,K], W:[K,64]) ---
template <int K>
__global__ __launch_bounds__(256, 2) void gemm_dual(const float* __restrict__ A,
                                                    const float* __restrict__ Wl,
                                                    const float* __restrict__ Wr,
                                                    float* __restrict__ outl,
                                                    float* __restrict__ outr) {
    constexpr int KC = 16;
    __shared__ __align__(16) float sA[KC * 132];   // [k][m]
    __shared__ __align__(16) float sW[KC * 128];   // [k][n]

    const int tid = threadIdx.x;
    const int mg = tid >> 4;
    const int ng = tid & 15;
    const int m_base = blockIdx.x * 128;

    float acc[8][8];
#pragma unroll
    for (int i = 0; i < 8; i++)
#pragma unroll
        for (int j = 0; j < 8; j++) acc[i][j] = 0.f;

    for (int kk = 0; kk < K; kk += KC) {
        __syncthreads();
#pragma unroll
        for (int j = 0; j < 8; j++) {
            int i = tid + 256 * j;
            int m = i >> 4;
            int k = i & 15;
            sA[k * 132 + m] = __ldg(A + (long)(m_base + m) * K + kk + k);
        }
#pragma unroll
        for (int j = 0; j < 8; j++) {
            int i = tid + 256 * j;
            int k = i >> 7;
            int n = i & 127;
            float w = (n < 64) ? __ldg(Wl + (long)(kk + k) * 64 + n)
                               : __ldg(Wr + (long)(kk + k) * 64 + (n - 64));
            sW[k * 128 + n] = w;
        }
        __syncthreads();

#pragma unroll 4
        for (int k = 0; k < KC; k++) {
            const float4* a4 = reinterpret_cast<const float4*>(sA + k * 132);
            const float4* w4 = reinterpret_cast<const float4*>(sW + k * 128);
            float4 a0 = a4[mg * 2], a1 = a4[mg * 2 + 1];
            float4 w0 = w4[ng * 2], w1 = w4[ng * 2 + 1];
            float av[8] = {a0.x, a0.y, a0.z, a0.w, a1.x, a1.y, a1.z, a1.w};
            float wv[8] = {w0.x, w0.y, w0.z, w0.w, w1.x, w1.y, w1.z, w1.w};
#pragma unroll
            for (int i = 0; i < 8; i++)
#pragma unroll
                for (int j = 0; j < 8; j++) acc[i][j] += av[i] * wv[j];
        }
    }

    float* outp = (ng < 8) ? outl : outr;
    int cb = (ng & 7) * 8;
#pragma unroll
    for (int i = 0; i < 8; i++) {
        long r = m_base + mg * 8 + i;
        float4* o4 = reinterpret_cast<float4*>(outp + r * ND + cb);
        o4[0] = make_float4(acc[i][0], acc[i][1], acc[i][2], acc[i][3]);
        o4[1] = make_float4(acc[i][4], acc[i][5], acc[i][6], acc[i][7]);
    }
}

// ---- CSR gather + fused SAGE epilogue: out = [relu](mean + b + self) -------
template <bool RELU>
__global__ __launch_bounds__(256) void gather_epi(const float* __restrict__ val,
                                                  const float* __restrict__ selfp,
                                                  const float* __restrict__ bias,
                                                  float* __restrict__ out) {
    int row = (blockIdx.x * 256 + threadIdx.x) >> 5;
    int lane = threadIdx.x & 31;
    int beg = __ldg(g_off + row);
    int end = __ldg(g_off + row + 1);
    const float2* v2 = reinterpret_cast<const float2*>(val);
    float2 a = make_float2(0.f, 0.f);
    int i = beg;
    for (; i + 4 <= end; i += 4) {
        int j0 = __ldg(g_nbr + i), j1 = __ldg(g_nbr + i + 1);
        int j2 = __ldg(g_nbr + i + 2), j3 = __ldg(g_nbr + i + 3);
        float2 x0 = __ldg(v2 + j0 * 32 + lane);
        float2 x1 = __ldg(v2 + j1 * 32 + lane);
        float2 x2 = __ldg(v2 + j2 * 32 + lane);
        float2 x3 = __ldg(v2 + j3 * 32 + lane);
        a.x += (x0.x + x1.x) + (x2.x + x3.x);
        a.y += (x0.y + x1.y) + (x2.y + x3.y);
    }
    for (; i < end; i++) {
        int j = __ldg(g_nbr + i);
        float2 x = __ldg(v2 + j * 32 + lane);
        a.x += x.x;
        a.y += x.y;
    }
    float inv = 1.f / fmaxf((float)(end - beg), 1.f);
    float2 b = __ldg(reinterpret_cast<const float2*>(bias) + lane);
    float2 s = __ldg(reinterpret_cast<const float2*>(selfp) + row * 32 + lane);
    float2 r = make_float2(a.x * inv + b.x + s.x, a.y * inv + b.y + s.y);
    if (RELU) { r.x = fmaxf(r.x, 0.f); r.y = fmaxf(r.y, 0.f); }
    reinterpret_cast<float2*>(out)[row * 32 + lane] = r;
}

// ---------------- cosine score + rank-16 feature map ------------------------
__global__ __launch_bounds__(256) void score_phi_kernel(const float* __restrict__ aux) {
    __shared__ float s_aux[ND];
    __shared__ float s_inv;
    if (threadIdx.x < ND) s_aux[threadIdx.x] = aux[threadIdx.x];
    __syncthreads();
    if (threadIdx.x == 0) {
        float ss = 0.f;
        for (int d = 0; d < ND; d++) ss += s_aux[d] * s_aux[d];
        s_inv = 1.f / fmaxf(sqrtf(ss), 1e-8f);
    }
    __syncthreads();
    int row = blockIdx.x * 256 + threadIdx.x;
    const float* h = g_h2 + (long)row * ND;
    float dot = 0.f, nn = 0.f;
#pragma unroll
    for (int d = 0; d < ND; d++) {
        float hv = __ldg(h + d);
        dot += hv * s_aux[d];
        nn += hv * hv;
    }
    float s = dot * s_inv / fmaxf(sqrtf(nn), 1e-8f);
    float e = expf(-s * s);
    float p = 1.f;
#pragma unroll
    for (int k = 0; k < RK; k++) {
        g_phi[(long)row * RK + k] = e * c_coef[k] * p;
        p *= s;
    }
}

// ---------------- T = Phi^T [h2 | 1]  (16 x 65) -----------------------------
__global__ __launch_bounds__(256) void phiT_kernel() {
    int gw = (blockIdx.x * 256 + threadIdx.x) >> 5;  // 512 warps total
    int lane = threadIdx.x & 31;
    float accA[RK], accB[RK];
#pragma unroll
    for (int k = 0; k < RK; k++) { accA[k] = 0.f; accB[k] = 0.f; }
    float accD = 0.f;
    const int rows_per_warp = NN / 512;  // 32
    int r0 = gw * rows_per_warp;
    for (int r = r0; r < r0 + rows_per_warp; r++) {
        float pv = (lane < RK) ? g_phi[(long)r * RK + lane] : 0.f;
        float v0 = g_h2[(long)r * ND + lane];
        float v1 = g_h2[(long)r * ND + 32 + lane];
        accD += pv;
#pragma unroll
        for (int k = 0; k < RK; k++) {
            float pk = __shfl_sync(0xffffffffu, pv, k);
            accA[k] += pk * v0;
            accB[k] += pk * v1;
        }
    }
#pragma unroll
    for (int k = 0; k < RK; k++) {
        atomicAdd(&g_T[k * 65 + lane], accA[k]);
        atomicAdd(&g_T[k * 65 + 32 + lane], accB[k]);
    }
    if (lane < RK) atomicAdd(&g_T[lane * 65 + 64], accD);
}

// ---------------- z = Phi T / den;  out = [h2|z] @ Wc + bc ------------------
__global__ __launch_bounds__(128) void final_kernel(const float* __restrict__ Wc,
                                                    const float* __restrict__ bc,
                                                    float* __restrict__ out) {
    __shared__ float Ts[RK * 65];
    __shared__ float Wcs[2 * ND * NC];
    __shared__ float bcs[NC];
    for (int i = threadIdx.x; i < RK * 65; i += 128) Ts[i] = g_T[i];
    for (int i = threadIdx.x; i < 2 * ND * NC; i += 128) Wcs[i] = Wc[i];
    if (threadIdx.x < NC) bcs[threadIdx.x] = bc[threadIdx.x];
    __syncthreads();
    int row = blockIdx.x * 128 + threadIdx.x;
    float phi[RK];
#pragma unroll
    for (int k = 0; k < RK; k++) phi[k] = g_phi[(long)row * RK + k];
    float den = 0.f;
#pragma unroll
    for (int k = 0; k < RK; k++) den += phi[k] * Ts[k * 65 + 64];
    float dinv = 1.f / den;
#pragma unroll
    for (int k = 0; k < RK; k++) phi[k] *= dinv;
    float o[NC];
#pragma unroll
    for (int c = 0; c < NC; c++) o[c] = bcs[c];
    const float* h = g_h2 + (long)row * ND;
#pragma unroll 2
    for (int d = 0; d < ND; d++) {
        float hv = __ldg(h + d);
        float zd = 0.f;
#pragma unroll
        for (int k = 0; k < RK; k++) zd += phi[k] * Ts[k * 65 + d];
        const float* w1 = Wcs + d * NC;
        const float* w2 = Wcs + (ND + d) * NC;
#pragma unroll
        for (int c = 0; c < NC; c++) o[c] += hv * w1[c] + zd * w2[c];
    }
    float* op = out + (long)row * NC;
#pragma unroll
    for (int c = 0; c < NC; c++) op[c] = o[c];
}

// ---------------------------------------------------------------------------
extern "C" void kernel_launch(void* const* d_in, const int* in_sizes, int n_in,
                              void* d_out, int out_size) {
    const float* x   = (const float*)d_in[0];
    const int*   ei  = (const int*)d_in[1];
    const float* W1l = (const float*)d_in[2];
    const float* b1  = (const float*)d_in[3];
    const float* W1r = (const float*)d_in[4];
    const float* W2l = (const float*)d_in[5];
    const float* b2  = (const float*)d_in[6];
    const float* W2r = (const float*)d_in[7];
    const float* aux = (const float*)d_in[8];
    const float* Wc  = (const float*)d_in[9];
    const float* bc  = (const float*)d_in[10];
    float* out = (float*)d_out;

    float *p_xl, *p_xr, *p_h1, *p_h1l, *p_h1r, *p_h2;
    cudaGetSymbolAddress((void**)&p_xl,   g_xl);
    cudaGetSymbolAddress((void**)&p_xr,   g_xr);
    cudaGetSymbolAddress((void**)&p_h1,   g_h1);
    cudaGetSymbolAddress((void**)&p_h1l,  g_h1l);
    cudaGetSymbolAddress((void**)&p_h1r,  g_h1r);
    cudaGetSymbolAddress((void**)&p_h2,   g_h2);

    // ---- CSR build (shared by both layers) ----
    zero_kernel<<<(NN + 1023) / 1024, 1024>>>();
    count_kernel<<<NE / 256, 256>>>(ei);
    scan_kernel<<<1, 1024>>>();
    fill_kernel<<<NE / 256, 256>>>(ei);

    // ---- layer 1: h1 = relu(mean_agg(x@W1l) + b1 + x@W1r) ----
    gemm_dual<NF><<<NN / 128, 256>>>(x, W1l, W1r, p_xl, p_xr);
    gather_epi<true><<<NN * 32 / 256, 256>>>(p_xl, p_xr, b1, p_h1);

    // ---- layer 2: h2 = mean_agg(h1@W2l) + b2 + h1@W2r ----
    gemm_dual<ND><<<NN / 128, 256>>>(p_h1, W2l, W2r, p_h1l, p_h1r);
    gather_epi<false><<<NN * 32 / 256, 256>>>(p_h1l, p_h1r, b2, p_h2);

    // ---- rank-16 separable Gaussian kernel aggregation ----
    score_phi_kernel<<<NN / 256, 256>>>(aux);
    phiT_kernel<<<64, 256>>>();

    // ---- z + classifier ----
    final_kernel<<<NN / 128, 128>>>(Wc, bc, out);
}

// round 4
// speedup vs baseline: 1.2024x; 1.2024x over previous
#include <cuda_runtime.h>
#include <math.h>

#define NN 16384
#define NE 262144
#define NF 128
#define ND 64
#define NC 40
#define RK 16
#define MAXDEG 64

// ---------------- scratch (device globals; no allocation allowed) ----------
__device__ float g_xl  [NN * ND];   // x @ W1l   (gathered in layer 1)
__device__ float g_xr  [NN * ND];   // x @ W1r   (self part layer 1)
__device__ float g_h1  [NN * ND];
__device__ float g_h1l [NN * ND];   // h1 @ W2l  (gathered in layer 2)
__device__ float g_h1r [NN * ND];   // h1 @ W2r  (self part layer 2)
__device__ float g_h2  [NN * ND];
__device__ float g_phi [NN * RK];
__device__ float g_T   [RK * 65];
__device__ int   g_deg [NN];
__device__ int   g_ell [NN * MAXDEG];

// c_k = sqrt(2^k / k!)
__constant__ float c_coef[RK] = {
    1.0f,          1.41421356f,  1.41421356f,  1.15470054f,
    0.81649658f,   0.51639778f,  0.29814240f,  0.15936387f,
    0.07968194f,   0.03756241f,  0.01679842f,  0.00716286f,
    0.00292422f,   0.00114698f,  4.33517e-4f,  1.58298e-4f};

// ---------------- zero degree counters + T ----------------------------------
__global__ void zero_kernel() {
    int idx = blockIdx.x * blockDim.x + threadIdx.x;
    if (idx < NN) g_deg[idx] = 0;
    if (idx < RK * 65) g_T[idx] = 0.f;
}

// ---------------- ELL fill: one atomic per edge ------------------------------
__global__ __launch_bounds__(256) void fill_ell(const int* __restrict__ ei) {
    int t = blockIdx.x * 256 + threadIdx.x;
    int src = __ldg(ei + t);
    int dst = __ldg(ei + NE + t);
    int slot = atomicAdd(g_deg + dst, 1) & (MAXDEG - 1);
    g_ell[dst * MAXDEG + slot] = src;
}

// ---- fused dual GEMM: outl = A @ Wl, outr = A @ Wr  (A:[NN,K], W:[K,64]) ---
// M-tile 64, 256 threads, thread tile 4x8, K chunked by 16 through smem.
template <int K>
__global__ __launch_bounds__(256) void gemm_dual(const float* __restrict__ A,
                                                 const float* __restrict__ Wl,
                                                 const float* __restrict__ Wr,
                                                 float* __restrict__ outl,
                                                 float* __restrict__ outr) {
    constexpr int KC = 16;
    __shared__ __align__(16) float sA[KC * 68];    // [k][m], 64 + pad4
    __shared__ __align__(16) float sW[KC * 128];   // [k][n]

    const int tid = threadIdx.x;
    const int mg = tid >> 4;          // 0..15 -> 4 rows each
    const int ng = tid & 15;          // 0..15 -> 8 cols each
    const int m_base = blockIdx.x * 64;

    float acc[4][8];
#pragma unroll
    for (int i = 0; i < 4; i++)
#pragma unroll
        for (int j = 0; j < 8; j++) acc[i][j] = 0.f;

    for (int kk = 0; kk < K; kk += KC) {
        __syncthreads();
        // A chunk transposed: 64 rows x 16 k  (1024 floats, 4/thread)
#pragma unroll
        for (int j = 0; j < 4; j++) {
            int i = tid + 256 * j;
            int m = i >> 4;
            int k = i & 15;
            sA[k * 68 + m] = __ldg(A + (long)(m_base + m) * K + kk + k);
        }
        // W chunk: 16 k x 128 n (2048 floats, 8/thread)
#pragma unroll
        for (int j = 0; j < 8; j++) {
            int i = tid + 256 * j;
            int k = i >> 7;
            int n = i & 127;
            float w = (n < 64) ? __ldg(Wl + (long)(kk + k) * 64 + n)
                               : __ldg(Wr + (long)(kk + k) * 64 + (n - 64));
            sW[k * 128 + n] = w;
        }
        __syncthreads();

#pragma unroll 4
        for (int k = 0; k < KC; k++) {
            float4 a = *reinterpret_cast<const float4*>(sA + k * 68 + mg * 4);
            const float4* w4 = reinterpret_cast<const float4*>(sW + k * 128);
            float4 w0 = w4[ng * 2], w1 = w4[ng * 2 + 1];
            float av[4] = {a.x, a.y, a.z, a.w};
            float wv[8] = {w0.x, w0.y, w0.z, w0.w, w1.x, w1.y, w1.z, w1.w};
#pragma unroll
            for (int i = 0; i < 4; i++)
#pragma unroll
                for (int j = 0; j < 8; j++) acc[i][j] += av[i] * wv[j];
        }
    }

    float* outp = (ng < 8) ? outl : outr;
    int cb = (ng & 7) * 8;
#pragma unroll
    for (int i = 0; i < 4; i++) {
        long r = m_base + mg * 4 + i;
        float4* o4 = reinterpret_cast<float4*>(outp + r * ND + cb);
        o4[0] = make_float4(acc[i][0], acc[i][1], acc[i][2], acc[i][3]);
        o4[1] = make_float4(acc[i][4], acc[i][5], acc[i][6], acc[i][7]);
    }
}

// ---- ELL gather + fused SAGE epilogue (+ optional phi computation) ---------
// warp per row; neighbor indices prefetched lane-parallel, broadcast by shfl.
template <bool RELU, bool PHI>
__global__ __launch_bounds__(256) void gather_epi(const float* __restrict__ val,
                                                  const float* __restrict__ selfp,
                                                  const float* __restrict__ bias,
                                                  const float* __restrict__ aux,
                                                  float* __restrict__ out) {
    __shared__ float2 s_aux2[32];
    __shared__ float s_ainv;
    int tid = threadIdx.x;
    int lane = tid & 31;
    if (PHI) {
        if (tid < 32) s_aux2[tid] = __ldg(reinterpret_cast<const float2*>(aux) + tid);
        __syncthreads();
        if (tid < 32) {
            float2 a = s_aux2[lane];
            float ss = a.x * a.x + a.y * a.y;
#pragma unroll
            for (int o = 16; o; o >>= 1) ss += __shfl_xor_sync(0xffffffffu, ss, o);
            if (lane == 0) s_ainv = 1.f / fmaxf(sqrtf(ss), 1e-8f);
        }
        __syncthreads();
    }

    int row = blockIdx.x * 8 + (tid >> 5);
    int deg = __ldg(g_deg + row);
    const float2* v2 = reinterpret_cast<const float2*>(val);

    int c0 = min(deg, 32);
    int j0 = (lane < c0) ? __ldg(g_ell + row * MAXDEG + lane) : 0;
    float2 a = make_float2(0.f, 0.f);
    int k = 0;
    for (; k + 4 <= c0; k += 4) {
        int a0 = __shfl_sync(0xffffffffu, j0, k);
        int a1 = __shfl_sync(0xffffffffu, j0, k + 1);
        int a2 = __shfl_sync(0xffffffffu, j0, k + 2);
        int a3 = __shfl_sync(0xffffffffu, j0, k + 3);
        float2 x0 = __ldg(v2 + a0 * 32 + lane);
        float2 x1 = __ldg(v2 + a1 * 32 + lane);
        float2 x2 = __ldg(v2 + a2 * 32 + lane);
        float2 x3 = __ldg(v2 + a3 * 32 + lane);
        a.x += (x0.x + x1.x) + (x2.x + x3.x);
        a.y += (x0.y + x1.y) + (x2.y + x3.y);
    }
    for (; k < c0; k++) {
        int aj = __shfl_sync(0xffffffffu, j0, k);
        float2 x = __ldg(v2 + aj * 32 + lane);
        a.x += x.x; a.y += x.y;
    }
    if (deg > 32) {
        int c1 = deg - 32;
        int j1 = (lane < c1) ? __ldg(g_ell + row * MAXDEG + 32 + lane) : 0;
        for (k = 0; k < c1; k++) {
            int aj = __shfl_sync(0xffffffffu, j1, k);
            float2 x = __ldg(v2 + aj * 32 + lane);
            a.x += x.x; a.y += x.y;
        }
    }

    float inv = 1.f / fmaxf((float)deg, 1.f);
    float2 b = __ldg(reinterpret_cast<const float2*>(bias) + lane);
    float2 s = __ldg(reinterpret_cast<const float2*>(selfp) + row * 32 + lane);
    float2 r = make_float2(a.x * inv + b.x + s.x, a.y * inv + b.y + s.y);
    if (RELU) { r.x = fmaxf(r.x, 0.f); r.y = fmaxf(r.y, 0.f); }
    reinterpret_cast<float2*>(out)[row * 32 + lane] = r;

    if (PHI) {
        float2 ax = s_aux2[lane];
        float dot = r.x * ax.x + r.y * ax.y;
        float nn = r.x * r.x + r.y * r.y;
#pragma unroll
        for (int o = 16; o; o >>= 1) {
            dot += __shfl_xor_sync(0xffffffffu, dot, o);
            nn  += __shfl_xor_sync(0xffffffffu, nn, o);
        }
        float sc = dot * s_ainv / fmaxf(sqrtf(nn), 1e-8f);
        float e = expf(-sc * sc);
        if (lane < RK) {
            float p = 1.f;
            for (int i = 0; i < lane; i++) p *= sc;
            g_phi[row * RK + lane] = e * c_coef[lane] * p;
        }
    }
}

// ---------------- T = Phi^T [h2 | 1]  (16 x 65) -----------------------------
__global__ __launch_bounds__(256) void phiT_kernel() {
    int gw = (blockIdx.x * 256 + threadIdx.x) >> 5;  // 512 warps total
    int lane = threadIdx.x & 31;
    float accA[RK], accB[RK];
#pragma unroll
    for (int k = 0; k < RK; k++) { accA[k] = 0.f; accB[k] = 0.f; }
    float accD = 0.f;
    const int rows_per_warp = NN / 512;  // 32
    int r0 = gw * rows_per_warp;
    for (int r = r0; r < r0 + rows_per_warp; r++) {
        float pv = (lane < RK) ? g_phi[(long)r * RK + lane] : 0.f;
        float v0 = g_h2[(long)r * ND + lane];
        float v1 = g_h2[(long)r * ND + 32 + lane];
        accD += pv;
#pragma unroll
        for (int k = 0; k < RK; k++) {
            float pk = __shfl_sync(0xffffffffu, pv, k);
            accA[k] += pk * v0;
            accB[k] += pk * v1;
        }
    }
#pragma unroll
    for (int k = 0; k < RK; k++) {
        atomicAdd(&g_T[k * 65 + lane], accA[k]);
        atomicAdd(&g_T[k * 65 + 32 + lane], accB[k]);
    }
    if (lane < RK) atomicAdd(&g_T[lane * 65 + 64], accD);
}

// ---------------- z = Phi T / den;  out = [h2|z] @ Wc + bc ------------------
__global__ __launch_bounds__(128) void final_kernel(const float* __restrict__ Wc,
                                                    const float* __restrict__ bc,
                                                    float* __restrict__ out) {
    __shared__ float Ts[RK * 65];
    __shared__ float Wcs[2 * ND * NC];
    __shared__ float bcs[NC];
    for (int i = threadIdx.x; i < RK * 65; i += 128) Ts[i] = g_T[i];
    for (int i = threadIdx.x; i < 2 * ND * NC; i += 128) Wcs[i] = Wc[i];
    if (threadIdx.x < NC) bcs[threadIdx.x] = bc[threadIdx.x];
    __syncthreads();
    int row = blockIdx.x * 128 + threadIdx.x;
    float phi[RK];
#pragma unroll
    for (int k = 0; k < RK; k++) phi[k] = g_phi[(long)row * RK + k];
    float den = 0.f;
#pragma unroll
    for (int k = 0; k < RK; k++) den += phi[k] * Ts[k * 65 + 64];
    float dinv = 1.f / den;
#pragma unroll
    for (int k = 0; k < RK; k++) phi[k] *= dinv;
    float o[NC];
#pragma unroll
    for (int c = 0; c < NC; c++) o[c] = bcs[c];
    const float* h = g_h2 + (long)row * ND;
#pragma unroll 2
    for (int d = 0; d < ND; d++) {
        float hv = __ldg(h + d);
        float zd = 0.f;
#pragma unroll
        for (int k = 0; k < RK; k++) zd += phi[k] * Ts[k * 65 + d];
        const float* w1 = Wcs + d * NC;
        const float* w2 = Wcs + (ND + d) * NC;
#pragma unroll
        for (int c = 0; c < NC; c++) o[c] += hv * w1[c] + zd * w2[c];
    }
    float* op = out + (long)row * NC;
#pragma unroll
    for (int c = 0; c < NC; c++) op[c] = o[c];
}

// ---------------------------------------------------------------------------
extern "C" void kernel_launch(void* const* d_in, const int* in_sizes, int n_in,
                              void* d_out, int out_size) {
    const float* x   = (const float*)d_in[0];
    const int*   ei  = (const int*)d_in[1];
    const float* W1l = (const float*)d_in[2];
    const float* b1  = (const float*)d_in[3];
    const float* W1r = (const float*)d_in[4];
    const float* W2l = (const float*)d_in[5];
    const float* b2  = (const float*)d_in[6];
    const float* W2r = (const float*)d_in[7];
    const float* aux = (const float*)d_in[8];
    const float* Wc  = (const float*)d_in[9];
    const float* bc  = (const float*)d_in[10];
    float* out = (float*)d_out;

    float *p_xl, *p_xr, *p_h1, *p_h1l, *p_h1r, *p_h2;
    cudaGetSymbolAddress((void**)&p_xl,   g_xl);
    cudaGetSymbolAddress((void**)&p_xr,   g_xr);
    cudaGetSymbolAddress((void**)&p_h1,   g_h1);
    cudaGetSymbolAddress((void**)&p_h1l,  g_h1l);
    cudaGetSymbolAddress((void**)&p_h1r,  g_h1r);
    cudaGetSymbolAddress((void**)&p_h2,   g_h2);

    // ---- ELL adjacency build (one atomic per edge; shared by both layers) --
    zero_kernel<<<64, 256>>>();
    fill_ell<<<NE / 256, 256>>>(ei);

    // ---- layer 1: h1 = relu(mean_agg(x@W1l) + b1 + x@W1r) ----
    gemm_dual<NF><<<NN / 64, 256>>>(x, W1l, W1r, p_xl, p_xr);
    gather_epi<true, false><<<NN / 8, 256>>>(p_xl, p_xr, b1, aux, p_h1);

    // ---- layer 2 + phi: h2 = mean_agg(h1@W2l) + b2 + h1@W2r ----
    gemm_dual<ND><<<NN / 64, 256>>>(p_h1, W2l, W2r, p_h1l, p_h1r);
    gather_epi<false, true><<<NN / 8, 256>>>(p_h1l, p_h1r, b2, aux, p_h2);

    // ---- T = Phi^T [h2|1], then z + classifier ----
    phiT_kernel<<<64, 256>>>();
    final_kernel<<<NN / 128, 128>>>(Wc, bc, out);
}

// round 5
// speedup vs baseline: 1.4479x; 1.2041x over previous
#include <cuda_runtime.h>
#include <math.h>

#define NN 16384
#define NE 262144
#define NF 128
#define ND 64
#define NC 40
#define RK 16
#define MAXDEG 64

typedef unsigned long long u64t;

// ---------------- packed f32x2 helpers (Blackwell) --------------------------
__device__ __forceinline__ u64t pk2(float lo, float hi) {
    u64t r; asm("mov.b64 %0, {%1, %2};" : "=l"(r) : "f"(lo), "f"(hi)); return r;
}
__device__ __forceinline__ void upk2(u64t v, float& lo, float& hi) {
    asm("mov.b64 {%0, %1}, %2;" : "=f"(lo), "=f"(hi) : "l"(v));
}
__device__ __forceinline__ void ffma2(u64t& d, u64t a, u64t b) {
    asm("fma.rn.f32x2 %0, %1, %2, %0;" : "+l"(d) : "l"(a), "l"(b));
}
__device__ __forceinline__ void fadd2(u64t& d, u64t a) {
    asm("add.rn.f32x2 %0, %0, %1;" : "+l"(d) : "l"(a));
}

// ---------------- scratch (device globals; zero at module load) -------------
__device__ float g_xl  [NN * ND];
__device__ float g_xr  [NN * ND];
__device__ float g_h1  [NN * ND];
__device__ float g_h1l [NN * ND];
__device__ float g_h1r [NN * ND];
__device__ float g_h2  [NN * ND];
__device__ float g_phi [NN * RK];
__device__ float g_T   [RK * 65];
__device__ int   g_deg [NN];        // zero at load; final_kernel re-zeros
__device__ int   g_ell [NN * MAXDEG];

// c_k = sqrt(2^k / k!)
__constant__ float c_coef[RK] = {
    1.0f,          1.41421356f,  1.41421356f,  1.15470054f,
    0.81649658f,   0.51639778f,  0.29814240f,  0.15936387f,
    0.07968194f,   0.03756241f,  0.01679842f,  0.00716286f,
    0.00292422f,   0.00114698f,  4.33517e-4f,  1.58298e-4f};

// ---- dual GEMM body: outl = A @ Wl, outr = A @ Wr  (A:[NN,K], W:[K,64]) ----
// 256 threads, M-tile 64, thread tile 4x8 (packed as 4x4 f32x2).
template <int K>
__device__ __forceinline__ void gemm_body(const float* __restrict__ A,
                                          const float* __restrict__ Wl,
                                          const float* __restrict__ Wr,
                                          float* __restrict__ outl,
                                          float* __restrict__ outr,
                                          int mblk) {
    constexpr int KC = 16;
    __shared__ __align__(16) float sA[KC * 68];
    __shared__ __align__(16) float sW[KC * 128];

    const int tid = threadIdx.x;
    const int mg = tid >> 4;
    const int ng = tid & 15;
    const int m_base = mblk * 64;

    u64t acc[4][4];
#pragma unroll
    for (int i = 0; i < 4; i++)
#pragma unroll
        for (int j = 0; j < 4; j++) acc[i][j] = 0ull;

    for (int kk = 0; kk < K; kk += KC) {
        __syncthreads();
#pragma unroll
        for (int j = 0; j < 4; j++) {
            int i = tid + 256 * j;
            int m = i >> 4;
            int k = i & 15;
            sA[k * 68 + m] = __ldg(A + (long)(m_base + m) * K + kk + k);
        }
#pragma unroll
        for (int j = 0; j < 8; j++) {
            int i = tid + 256 * j;
            int k = i >> 7;
            int n = i & 127;
            float w = (n < 64) ? __ldg(Wl + (long)(kk + k) * 64 + n)
                               : __ldg(Wr + (long)(kk + k) * 64 + (n - 64));
            sW[k * 128 + n] = w;
        }
        __syncthreads();

#pragma unroll
        for (int k = 0; k < KC; k++) {
            float4 a = *reinterpret_cast<const float4*>(sA + k * 68 + mg * 4);
            const float4* w4 = reinterpret_cast<const float4*>(sW + k * 128);
            float4 w0 = w4[ng * 2], w1 = w4[ng * 2 + 1];
            u64t wp[4] = {pk2(w0.x, w0.y), pk2(w0.z, w0.w),
                          pk2(w1.x, w1.y), pk2(w1.z, w1.w)};
            u64t ap[4] = {pk2(a.x, a.x), pk2(a.y, a.y),
                          pk2(a.z, a.z), pk2(a.w, a.w)};
#pragma unroll
            for (int i = 0; i < 4; i++)
#pragma unroll
                for (int j = 0; j < 4; j++) ffma2(acc[i][j], ap[i], wp[j]);
        }
    }

    float* outp = (ng < 8) ? outl : outr;
    int cb = (ng & 7) * 8;
#pragma unroll
    for (int i = 0; i < 4; i++) {
        long r = m_base + mg * 4 + i;
        float o0, o1, o2, o3, o4v, o5, o6, o7;
        upk2(acc[i][0], o0, o1); upk2(acc[i][1], o2, o3);
        upk2(acc[i][2], o4v, o5); upk2(acc[i][3], o6, o7);
        float4* o4 = reinterpret_cast<float4*>(outp + r * ND + cb);
        o4[0] = make_float4(o0, o1, o2, o3);
        o4[1] = make_float4(o4v, o5, o6, o7);
    }
}

// ---- fused launch 1: blocks [0,256) gemm1, blocks [256,1280) ELL fill ------
__global__ __launch_bounds__(256) void fused1(const float* __restrict__ x,
                                              const float* __restrict__ W1l,
                                              const float* __restrict__ W1r,
                                              const int* __restrict__ ei) {
    if (blockIdx.x < NN / 64) {
        gemm_body<NF>(x, W1l, W1r, g_xl, g_xr, blockIdx.x);
    } else {
        int t = (blockIdx.x - NN / 64) * 256 + threadIdx.x;
        int src = __ldg(ei + t);
        int dst = __ldg(ei + NE + t);
        int slot = atomicAdd(g_deg + dst, 1) & (MAXDEG - 1);
        g_ell[dst * MAXDEG + slot] = src;
    }
}

__global__ __launch_bounds__(256) void gemm2_kernel(const float* __restrict__ W2l,
                                                    const float* __restrict__ W2r) {
    gemm_body<ND>(g_h1, W2l, W2r, g_h1l, g_h1r, blockIdx.x);
}

// ---- ELL gather + fused SAGE epilogue (+ optional phi / g_T zero) ----------
template <bool RELU, bool PHI, bool ZEROT>
__global__ __launch_bounds__(256) void gather_epi(const float* __restrict__ val,
                                                  const float* __restrict__ selfp,
                                                  const float* __restrict__ bias,
                                                  const float* __restrict__ aux,
                                                  float* __restrict__ out) {
    if (ZEROT && blockIdx.x == 0) {
        for (int i = threadIdx.x; i < RK * 65; i += 256) g_T[i] = 0.f;
    }
    __shared__ float2 s_aux2[32];
    __shared__ float s_ainv;
    int tid = threadIdx.x;
    int lane = tid & 31;
    if (PHI) {
        if (tid < 32) s_aux2[tid] = __ldg(reinterpret_cast<const float2*>(aux) + tid);
        __syncthreads();
        if (tid < 32) {
            float2 a = s_aux2[lane];
            float ss = a.x * a.x + a.y * a.y;
#pragma unroll
            for (int o = 16; o; o >>= 1) ss += __shfl_xor_sync(0xffffffffu, ss, o);
            if (lane == 0) s_ainv = 1.f / fmaxf(sqrtf(ss), 1e-8f);
        }
        __syncthreads();
    }

    int row = blockIdx.x * 8 + (tid >> 5);
    int deg = __ldg(g_deg + row);
    const u64t* v8 = reinterpret_cast<const u64t*>(val);

    int c0 = min(deg, 32);
    int j0 = 0;
    if (lane < c0) j0 = __ldg(g_ell + row * MAXDEG + lane) * 32;  // pre-scaled
    u64t acc = 0ull;
    int k = 0;
    for (; k + 4 <= c0; k += 4) {
        int a0 = __shfl_sync(0xffffffffu, j0, k);
        int a1 = __shfl_sync(0xffffffffu, j0, k + 1);
        int a2 = __shfl_sync(0xffffffffu, j0, k + 2);
        int a3 = __shfl_sync(0xffffffffu, j0, k + 3);
        u64t x0 = __ldg(v8 + a0 + lane);
        u64t x1 = __ldg(v8 + a1 + lane);
        u64t x2 = __ldg(v8 + a2 + lane);
        u64t x3 = __ldg(v8 + a3 + lane);
        fadd2(acc, x0); fadd2(acc, x1); fadd2(acc, x2); fadd2(acc, x3);
    }
    for (; k < c0; k++) {
        int aj = __shfl_sync(0xffffffffu, j0, k);
        u64t x = __ldg(v8 + aj + lane);
        fadd2(acc, x);
    }
    if (deg > 32) {
        int c1 = deg - 32;
        int j1 = 0;
        if (lane < c1) j1 = __ldg(g_ell + row * MAXDEG + 32 + lane) * 32;
        for (k = 0; k < c1; k++) {
            int aj = __shfl_sync(0xffffffffu, j1, k);
            u64t x = __ldg(v8 + aj + lane);
            fadd2(acc, x);
        }
    }

    float ax, ay;
    upk2(acc, ax, ay);
    float inv = 1.f / fmaxf((float)deg, 1.f);
    float2 b = __ldg(reinterpret_cast<const float2*>(bias) + lane);
    float2 s = __ldg(reinterpret_cast<const float2*>(selfp) + row * 32 + lane);
    float2 r = make_float2(ax * inv + b.x + s.x, ay * inv + b.y + s.y);
    if (RELU) { r.x = fmaxf(r.x, 0.f); r.y = fmaxf(r.y, 0.f); }
    reinterpret_cast<float2*>(out)[row * 32 + lane] = r;

    if (PHI) {
        float2 axv = s_aux2[lane];
        float dot = r.x * axv.x + r.y * axv.y;
        float nn = r.x * r.x + r.y * r.y;
#pragma unroll
        for (int o = 16; o; o >>= 1) {
            dot += __shfl_xor_sync(0xffffffffu, dot, o);
            nn  += __shfl_xor_sync(0xffffffffu, nn, o);
        }
        float sc = dot * s_ainv / fmaxf(sqrtf(nn), 1e-8f);
        float e = expf(-sc * sc);
        if (lane < RK) {
            float p = 1.f;
            for (int i = 0; i < lane; i++) p *= sc;
            g_phi[row * RK + lane] = e * c_coef[lane] * p;
        }
    }
}

// ---------------- T = Phi^T [h2 | 1]  (16 x 65) -----------------------------
__global__ __launch_bounds__(256) void phiT_kernel() {
    int gw = (blockIdx.x * 256 + threadIdx.x) >> 5;
    int lane = threadIdx.x & 31;
    float accA[RK], accB[RK];
#pragma unroll
    for (int k = 0; k < RK; k++) { accA[k] = 0.f; accB[k] = 0.f; }
    float accD = 0.f;
    const int rows_per_warp = NN / 512;
    int r0 = gw * rows_per_warp;
    for (int r = r0; r < r0 + rows_per_warp; r++) {
        float pv = (lane < RK) ? g_phi[(long)r * RK + lane] : 0.f;
        float v0 = g_h2[(long)r * ND + lane];
        float v1 = g_h2[(long)r * ND + 32 + lane];
        accD += pv;
#pragma unroll
        for (int k = 0; k < RK; k++) {
            float pk = __shfl_sync(0xffffffffu, pv, k);
            accA[k] += pk * v0;
            accB[k] += pk * v1;
        }
    }
#pragma unroll
    for (int k = 0; k < RK; k++) {
        atomicAdd(&g_T[k * 65 + lane], accA[k]);
        atomicAdd(&g_T[k * 65 + 32 + lane], accB[k]);
    }
    if (lane < RK) atomicAdd(&g_T[lane * 65 + 64], accD);
}

// ------ z = Phi T / den;  out = [h2|z] @ Wc + bc;  reset g_deg --------------
__global__ __launch_bounds__(128) void final_kernel(const float* __restrict__ Wc,
                                                    const float* __restrict__ bc,
                                                    float* __restrict__ out) {
    __shared__ float Ts[RK * 65];
    __shared__ u64t Wp[128 * 20];
    __shared__ u64t bp[20];
    int tid = threadIdx.x;
    for (int i = tid; i < RK * 65; i += 128) Ts[i] = g_T[i];
    for (int i = tid; i < 128 * 20; i += 128) {
        int d = i / 20, c = i % 20;
        Wp[i] = pk2(__ldg(Wc + d * NC + 2 * c), __ldg(Wc + d * NC + 2 * c + 1));
    }
    if (tid < 20) bp[tid] = pk2(bc[2 * tid], bc[2 * tid + 1]);
    __syncthreads();

    int row = blockIdx.x * 128 + tid;
    float phi[RK];
#pragma unroll
    for (int k = 0; k < RK; k++) phi[k] = g_phi[(long)row * RK + k];
    float den = 0.f;
#pragma unroll
    for (int k = 0; k < RK; k++) den += phi[k] * Ts[k * 65 + 64];
    float dinv = 1.f / den;
#pragma unroll
    for (int k = 0; k < RK; k++) phi[k] *= dinv;

    u64t o[20];
#pragma unroll
    for (int c = 0; c < 20; c++) o[c] = bp[c];
    const float* h = g_h2 + (long)row * ND;
#pragma unroll 2
    for (int d = 0; d < ND; d++) {
        float hv = __ldg(h + d);
        float zd = 0.f;
#pragma unroll
        for (int k = 0; k < RK; k++) zd += phi[k] * Ts[k * 65 + d];
        u64t hv2 = pk2(hv, hv), zd2 = pk2(zd, zd);
        const u64t* w1 = Wp + d * 20;
        const u64t* w2 = Wp + (ND + d) * 20;
#pragma unroll
        for (int c = 0; c < 20; c++) {
            ffma2(o[c], hv2, w1[c]);
            ffma2(o[c], zd2, w2[c]);
        }
    }
    float* op = out + (long)row * NC;
#pragma unroll
    for (int c = 0; c < 10; c++) {
        float v0, v1, v2, v3;
        upk2(o[2 * c], v0, v1);
        upk2(o[2 * c + 1], v2, v3);
        reinterpret_cast<float4*>(op)[c] = make_float4(v0, v1, v2, v3);
    }
    g_deg[row] = 0;   // restore invariant for next call
}

// ---------------------------------------------------------------------------
extern "C" void kernel_launch(void* const* d_in, const int* in_sizes, int n_in,
                              void* d_out, int out_size) {
    const float* x   = (const float*)d_in[0];
    const int*   ei  = (const int*)d_in[1];
    const float* W1l = (const float*)d_in[2];
    const float* b1  = (const float*)d_in[3];
    const float* W1r = (const float*)d_in[4];
    const float* W2l = (const float*)d_in[5];
    const float* b2  = (const float*)d_in[6];
    const float* W2r = (const float*)d_in[7];
    const float* aux = (const float*)d_in[8];
    const float* Wc  = (const float*)d_in[9];
    const float* bc  = (const float*)d_in[10];
    float* out = (float*)d_out;

    float *p_xl, *p_xr, *p_h1, *p_h1l, *p_h1r, *p_h2;
    cudaGetSymbolAddress((void**)&p_xl,   g_xl);
    cudaGetSymbolAddress((void**)&p_xr,   g_xr);
    cudaGetSymbolAddress((void**)&p_h1,   g_h1);
    cudaGetSymbolAddress((void**)&p_h1l,  g_h1l);
    cudaGetSymbolAddress((void**)&p_h1r,  g_h1r);
    cudaGetSymbolAddress((void**)&p_h2,   g_h2);

    // 1) gemm1 (x@[W1l|W1r]) concurrently with ELL build (g_deg pre-zeroed)
    fused1<<<NN / 64 + NE / 256, 256>>>(x, W1l, W1r, ei);
    // 2) layer-1 gather+epi (also zeroes g_T for phiT)
    gather_epi<true, false, true><<<NN / 8, 256>>>(p_xl, p_xr, b1, aux, p_h1);
    // 3) gemm2
    gemm2_kernel<<<NN / 64, 256>>>(W2l, W2r);
    // 4) layer-2 gather+epi + phi
    gather_epi<false, true, false><<<NN / 8, 256>>>(p_h1l, p_h1r, b2, aux, p_h2);
    // 5) T = Phi^T [h2|1]
    phiT_kernel<<<64, 256>>>();
    // 6) classifier (+ g_deg reset)
    final_kernel<<<NN / 128, 128>>>(Wc, bc, out);
}